// round 1
// baseline (speedup 1.0000x reference)
#include <cuda_runtime.h>
#include <stdint.h>

#define NN   100000
#define INC  256
#define HIDC 64
#define HR   192   // 3*HID concat row
#define OC   40

// Scratch: H[r] = [h0 (0..63) | h1 (64..127) | h2 (128..191)]  -- 76.8 MB, L2-resident
static __device__ float g_H[(size_t)NN * HR];

// ---------------------------------------------------------------------------
// Zero the scratch (atomic destinations must start at 0 every replay)
// ---------------------------------------------------------------------------
__global__ void zero_H() {
    size_t i = (size_t)blockIdx.x * blockDim.x + threadIdx.x;
    const size_t n4 = (size_t)NN * HR / 4;
    if (i < n4) reinterpret_cast<float4*>(g_H)[i] = make_float4(0.f, 0.f, 0.f, 0.f);
}

// ---------------------------------------------------------------------------
// GEMM1: h0 = x @ fc1_w^T      x[NN,256], w[64,256] -> H[:, 0:64]
// 64x64 output tile per block, BK=64, thread = 4x4, k-major dot-product form
// ---------------------------------------------------------------------------
__global__ __launch_bounds__(256) void gemm1(const float* __restrict__ x,
                                             const float* __restrict__ w) {
    __shared__ float xs[64][68];   // rows x k (pad 68: 16B-aligned rows, 2-way max conflict)
    __shared__ float ws[64][68];   // cols x k
    const int tid = threadIdx.x;
    const int tx = tid & 15;       // col-thread 0..15  -> cols tx*4..tx*4+3
    const int ty = tid >> 4;       // row-thread 0..15  -> rows ty*4..ty*4+3
    const int row0 = blockIdx.x * 64;

    float acc[4][4];
#pragma unroll
    for (int i = 0; i < 4; i++)
#pragma unroll
        for (int j = 0; j < 4; j++) acc[i][j] = 0.f;

    for (int k0 = 0; k0 < INC; k0 += 64) {
#pragma unroll
        for (int q = 0; q < 4; q++) {
            int f  = tid + q * 256;        // 0..1023 float4 slots
            int r  = f >> 4;               // 0..63
            int k4 = f & 15;               // 0..15
            float4 xv = make_float4(0.f, 0.f, 0.f, 0.f);
            int gr = row0 + r;
            if (gr < NN)
                xv = *reinterpret_cast<const float4*>(x + (size_t)gr * INC + k0 + k4 * 4);
            *reinterpret_cast<float4*>(&xs[r][k4 * 4]) = xv;
            float4 wv = *reinterpret_cast<const float4*>(w + (size_t)r * INC + k0 + k4 * 4);
            *reinterpret_cast<float4*>(&ws[r][k4 * 4]) = wv;
        }
        __syncthreads();
#pragma unroll
        for (int k4 = 0; k4 < 16; k4++) {
            float4 a[4], b[4];
#pragma unroll
            for (int i = 0; i < 4; i++)
                a[i] = *reinterpret_cast<const float4*>(&xs[ty * 4 + i][k4 * 4]);
#pragma unroll
            for (int j = 0; j < 4; j++)
                b[j] = *reinterpret_cast<const float4*>(&ws[tx * 4 + j][k4 * 4]);
#pragma unroll
            for (int i = 0; i < 4; i++)
#pragma unroll
                for (int j = 0; j < 4; j++)
                    acc[i][j] += a[i].x * b[j].x + a[i].y * b[j].y +
                                 a[i].z * b[j].z + a[i].w * b[j].w;
        }
        __syncthreads();
    }
#pragma unroll
    for (int i = 0; i < 4; i++) {
        int gr = row0 + ty * 4 + i;
        if (gr < NN) {
#pragma unroll
            for (int j = 0; j < 4; j++)
                g_H[(size_t)gr * HR + tx * 4 + j] = acc[i][j];
        }
    }
}

// ---------------------------------------------------------------------------
// SPMM: H[rows[e], dst_off:dst_off+64] += vals[e] * H[cols[e], 0:64]
// Half-warp per edge: 16 lanes x float4 = 64 floats. Vectorized L2 reduction.
// ---------------------------------------------------------------------------
__global__ void spmm(const int* __restrict__ rows, const int* __restrict__ cols,
                     const float* __restrict__ vals, int E, int dst_off) {
    int warp = (int)((blockIdx.x * blockDim.x + threadIdx.x) >> 5);
    int lane = threadIdx.x & 31;
    int sub  = lane >> 4;          // which edge of the pair
    int l    = lane & 15;          // float4 slot within row
    int e    = warp * 2 + sub;
    if (e >= E) return;
    int   r = __ldg(rows + e);
    int   c = __ldg(cols + e);
    float v = __ldg(vals + e);
    float4 h = *reinterpret_cast<const float4*>(g_H + (size_t)c * HR + l * 4);
    float4 p = make_float4(h.x * v, h.y * v, h.z * v, h.w * v);
    float* dst = g_H + (size_t)r * HR + dst_off + l * 4;
    asm volatile("red.global.add.v4.f32 [%0], {%1,%2,%3,%4};"
                 :: "l"(dst), "f"(p.x), "f"(p.y), "f"(p.z), "f"(p.w)
                 : "memory");
}

// ---------------------------------------------------------------------------
// GEMM2: out = H @ fc_out_w^T + b     H[NN,192], w[40,192] -> out[NN,40]
// Block = 128 rows. Thread = 4 rows x 5 cols; weight float4s reused 4x.
// ---------------------------------------------------------------------------
__global__ __launch_bounds__(256) void gemm2(const float* __restrict__ w,
                                             const float* __restrict__ b,
                                             float* __restrict__ out) {
    __shared__ float ws[OC][196];   // pad 196: 16B-aligned rows, conflict-free col spread
    __shared__ float bs[OC];
    const int tid = threadIdx.x;
    for (int f = tid; f < OC * 48; f += 256) {
        int c = f / 48, k4 = f % 48;
        *reinterpret_cast<float4*>(&ws[c][k4 * 4]) =
            *reinterpret_cast<const float4*>(w + (size_t)c * HR + k4 * 4);
    }
    if (tid < OC) bs[tid] = b[tid];
    __syncthreads();

    const int rt = tid >> 3;              // 0..31
    const int cg = tid & 7;               // 0..7 -> cols cg*5 .. cg*5+4
    const int r0 = blockIdx.x * 128 + rt * 4;

    float acc[4][5];
#pragma unroll
    for (int i = 0; i < 4; i++)
#pragma unroll
        for (int j = 0; j < 5; j++) acc[i][j] = 0.f;

#pragma unroll 4
    for (int k4 = 0; k4 < 48; k4++) {
        float4 wv[5];
#pragma unroll
        for (int j = 0; j < 5; j++)
            wv[j] = *reinterpret_cast<const float4*>(&ws[cg * 5 + j][k4 * 4]);
#pragma unroll
        for (int i = 0; i < 4; i++) {
            int r = r0 + i;
            if (r < NN) {
                float4 h = *reinterpret_cast<const float4*>(g_H + (size_t)r * HR + k4 * 4);
#pragma unroll
                for (int j = 0; j < 5; j++)
                    acc[i][j] += h.x * wv[j].x + h.y * wv[j].y +
                                 h.z * wv[j].z + h.w * wv[j].w;
            }
        }
    }
#pragma unroll
    for (int i = 0; i < 4; i++) {
        int r = r0 + i;
        if (r < NN) {
#pragma unroll
            for (int j = 0; j < 5; j++)
                out[(size_t)r * OC + cg * 5 + j] = acc[i][j] + bs[cg * 5 + j];
        }
    }
}

// ---------------------------------------------------------------------------
// Launch: zero -> gemm1 -> spmm(adj) -> spmm(adj2) -> gemm2
// Inputs (metadata order): x, edge_index(unused), adj_src, adj_dst, adj_val,
//                          adj2_src, adj2_dst, adj2_val, fc1_w, fc_out_w, fc_out_b
// ---------------------------------------------------------------------------
extern "C" void kernel_launch(void* const* d_in, const int* in_sizes, int n_in,
                              void* d_out, int out_size) {
    const float* x   = (const float*)d_in[0];
    const int*   a1r = (const int*)  d_in[2];
    const int*   a1c = (const int*)  d_in[3];
    const float* a1v = (const float*)d_in[4];
    const int*   a2r = (const int*)  d_in[5];
    const int*   a2c = (const int*)  d_in[6];
    const float* a2v = (const float*)d_in[7];
    const float* w1  = (const float*)d_in[8];
    const float* w2  = (const float*)d_in[9];
    const float* b2  = (const float*)d_in[10];
    float* out = (float*)d_out;
    const int E1 = in_sizes[4];
    const int E2 = in_sizes[7];

    {
        const size_t n4 = (size_t)NN * HR / 4;
        zero_H<<<(unsigned)((n4 + 255) / 256), 256>>>();
    }
    gemm1<<<(NN + 63) / 64, 256>>>(x, w1);
    {
        int warps1  = (E1 + 1) / 2;
        int blocks1 = (warps1 + 7) / 8;
        spmm<<<blocks1, 256>>>(a1r, a1c, a1v, E1, 64);
        int warps2  = (E2 + 1) / 2;
        int blocks2 = (warps2 + 7) / 8;
        spmm<<<blocks2, 256>>>(a2r, a2c, a2v, E2, 128);
    }
    gemm2<<<(NN + 127) / 128, 256>>>(w2, b2, out);
}

// round 2
// speedup vs baseline: 1.4701x; 1.4701x over previous
#include <cuda_runtime.h>
#include <stdint.h>

#define NN   100000
#define INC  256
#define HIDC 64
#define HR   192   // 3*HID concat row
#define OC   40

// Scratch: H[r] = [h0 (0..63) | h1 (64..127) | h2 (128..191)] -- 76.8MB, L2-resident
static __device__ float g_H[(size_t)NN * HR];

// ---------------- packed fp32 helpers (FFMA2 via PTX fma.rn.f32x2) ----------
__device__ __forceinline__ unsigned long long fma2(unsigned long long a,
                                                   unsigned long long b,
                                                   unsigned long long c) {
    unsigned long long d;
    asm("fma.rn.f32x2 %0, %1, %2, %3;" : "=l"(d) : "l"(a), "l"(b), "l"(c));
    return d;
}
__device__ __forceinline__ unsigned long long dup2(float x) {
    unsigned long long d;
    asm("mov.b64 %0, {%1, %1};" : "=l"(d) : "f"(x));
    return d;
}
__device__ __forceinline__ float2 unpk(unsigned long long v) {
    float2 r;
    asm("mov.b64 {%0, %1}, %2;" : "=f"(r.x), "=f"(r.y) : "l"(v));
    return r;
}

// ---------------------------------------------------------------------------
// GEMM1: h0 = x @ fc1_w^T    x[NN,256], w[64,256] -> H[:,0:64]; zero H[:,64:192]
// Tile 128x64, thread = 8 rows x 4 cols (2 packed pairs), K-chunk 32.
// B transposed in smem -> conflict-free float4 b-loads; FFMA2 for 2x fp32 rate.
// ---------------------------------------------------------------------------
__global__ __launch_bounds__(256) void gemm1(const float* __restrict__ x,
                                             const float* __restrict__ w) {
    __shared__ __align__(16) float xs[128][36];   // [row][k-chunk], pad->144B rows
    __shared__ __align__(16) float ws_t[32][68];  // [k][n], pad->272B rows
    const int tid = threadIdx.x;
    const int tx = tid & 15;        // cols tx*4..tx*4+3
    const int ty = tid >> 4;        // rows ty*8..ty*8+7
    const int row0 = blockIdx.x * 128;

    unsigned long long acc0[8], acc1[8];
#pragma unroll
    for (int i = 0; i < 8; i++) { acc0[i] = 0ULL; acc1[i] = 0ULL; }

    for (int k0 = 0; k0 < INC; k0 += 32) {
        // stage x tile: 1024 float4, coalesced (k4-fast)
#pragma unroll
        for (int q = 0; q < 4; q++) {
            int f  = tid + q * 256;
            int k4 = f & 7;
            int r  = f >> 3;
            int gr = min(row0 + r, NN - 1);
            float4 xv = *reinterpret_cast<const float4*>(x + (size_t)gr * INC + k0 + k4 * 4);
            *reinterpret_cast<float4*>(&xs[r][k4 * 4]) = xv;
        }
        // stage w tile transposed
#pragma unroll
        for (int q = 0; q < 2; q++) {
            int f  = tid + q * 256;
            int k4 = f & 7;
            int n  = f >> 3;
            float4 wv = *reinterpret_cast<const float4*>(w + (size_t)n * INC + k0 + k4 * 4);
            ws_t[k4 * 4 + 0][n] = wv.x;
            ws_t[k4 * 4 + 1][n] = wv.y;
            ws_t[k4 * 4 + 2][n] = wv.z;
            ws_t[k4 * 4 + 3][n] = wv.w;
        }
        __syncthreads();
#pragma unroll 2
        for (int k4 = 0; k4 < 8; k4++) {
            ulonglong2 bb[4];
#pragma unroll
            for (int k = 0; k < 4; k++)
                bb[k] = *reinterpret_cast<const ulonglong2*>(&ws_t[k4 * 4 + k][tx * 4]);
#pragma unroll
            for (int i = 0; i < 8; i++) {
                float4 a4 = *reinterpret_cast<const float4*>(&xs[ty * 8 + i][k4 * 4]);
                unsigned long long aa;
                aa = dup2(a4.x); acc0[i] = fma2(aa, bb[0].x, acc0[i]); acc1[i] = fma2(aa, bb[0].y, acc1[i]);
                aa = dup2(a4.y); acc0[i] = fma2(aa, bb[1].x, acc0[i]); acc1[i] = fma2(aa, bb[1].y, acc1[i]);
                aa = dup2(a4.z); acc0[i] = fma2(aa, bb[2].x, acc0[i]); acc1[i] = fma2(aa, bb[2].y, acc1[i]);
                aa = dup2(a4.w); acc0[i] = fma2(aa, bb[3].x, acc0[i]); acc1[i] = fma2(aa, bb[3].y, acc1[i]);
            }
        }
        __syncthreads();
    }
    // epilogue: h0 + fused zeroing of h1/h2 regions
#pragma unroll
    for (int i = 0; i < 8; i++) {
        int gr = row0 + ty * 8 + i;
        if (gr < NN) {
            float2 lo = unpk(acc0[i]);
            float2 hi = unpk(acc1[i]);
            *reinterpret_cast<float4*>(g_H + (size_t)gr * HR + tx * 4) =
                make_float4(lo.x, lo.y, hi.x, hi.y);
            const float4 z = make_float4(0.f, 0.f, 0.f, 0.f);
            *reinterpret_cast<float4*>(g_H + (size_t)gr * HR + 64  + tx * 4) = z;
            *reinterpret_cast<float4*>(g_H + (size_t)gr * HR + 128 + tx * 4) = z;
        }
    }
}

// ---------------------------------------------------------------------------
// SPMM (both graphs, one launch):
//   H[src[e], off:off+64] += val[e] * H[dst[e], 0:64]
// Warp = 8 edges. Lanes 0..7 load edge data once; shfl distributes.
// Half-warp x float4 covers a 64-float row; 4 gathers in flight (MLP=4).
// ---------------------------------------------------------------------------
__global__ void spmm_both(const int* __restrict__ r1, const int* __restrict__ c1,
                          const float* __restrict__ v1, int E1,
                          const int* __restrict__ r2, const int* __restrict__ c2,
                          const float* __restrict__ v2, int E2, int W1, int Wt) {
    int gw = (int)((blockIdx.x * blockDim.x + threadIdx.x) >> 5);
    if (gw >= Wt) return;
    const int*   R; const int* C; const float* V; int E, off, e0;
    if (gw < W1) { R = r1; C = c1; V = v1; E = E1; off = 64;  e0 = gw * 8; }
    else         { R = r2; C = c2; V = v2; E = E2; off = 128; e0 = (gw - W1) * 8; }

    const int lane = threadIdx.x & 31;
    const int le   = lane & 7;
    int   rr = 0, cc = 0;
    float vv = 0.f;
    if (lane < 8) {
        int e = e0 + le;
        int ec = min(e, E - 1);
        rr = __ldg(R + ec);
        cc = __ldg(C + ec);
        vv = (e < E) ? __ldg(V + ec) : 0.f;
    }
    const int sub = lane >> 4;      // which edge group in half-warp
    const int l   = lane & 15;      // float4 slot within 64-float row
    float4 p[4];
#pragma unroll
    for (int j = 0; j < 4; j++) {
        int src = sub * 4 + j;
        int   c = __shfl_sync(0xffffffffu, cc, src);
        float v = __shfl_sync(0xffffffffu, vv, src);
        float4 h = *reinterpret_cast<const float4*>(g_H + (size_t)c * HR + l * 4);
        p[j] = make_float4(h.x * v, h.y * v, h.z * v, h.w * v);
    }
#pragma unroll
    for (int j = 0; j < 4; j++) {
        int src = sub * 4 + j;
        int r   = __shfl_sync(0xffffffffu, rr, src);
        float* dst = g_H + (size_t)r * HR + off + l * 4;
        asm volatile("red.global.add.v4.f32 [%0], {%1,%2,%3,%4};"
                     :: "l"(dst), "f"(p[j].x), "f"(p[j].y), "f"(p[j].z), "f"(p[j].w)
                     : "memory");
    }
}

// ---------------------------------------------------------------------------
// GEMM2: out = H @ fc_out_w^T + b    H[NN,192], w[40,192] -> out[NN,40]
// Thread = 1 row x 40 cols (20 packed pairs). Weights transposed in smem,
// uniform broadcast loads; FFMA2.
// ---------------------------------------------------------------------------
__global__ __launch_bounds__(256) void gemm2(const float* __restrict__ w,
                                             const float* __restrict__ b,
                                             float* __restrict__ out) {
    __shared__ __align__(16) float w_t[HR][44];   // [k][oc], pad->176B rows
    __shared__ float bs[OC];
    const int tid = threadIdx.x;
    for (int idx = tid; idx < OC * HR; idx += 256) {
        int oc = idx / HR;
        int k  = idx - oc * HR;
        w_t[k][oc] = w[idx];          // w row-major [oc][k] -> coalesced read
    }
    if (tid < OC) bs[tid] = b[tid];
    __syncthreads();

    const int r  = blockIdx.x * 256 + tid;
    const int rr = min(r, NN - 1);
    const float* hrow = g_H + (size_t)rr * HR;

    unsigned long long acc[20];
#pragma unroll
    for (int p = 0; p < 20; p++) acc[p] = 0ULL;

#pragma unroll 4
    for (int k4 = 0; k4 < 48; k4++) {
        float4 h4 = *reinterpret_cast<const float4*>(hrow + k4 * 4);
        float hk[4] = {h4.x, h4.y, h4.z, h4.w};
#pragma unroll
        for (int k = 0; k < 4; k++) {
            unsigned long long hh = dup2(hk[k]);
#pragma unroll
            for (int p = 0; p < 10; p++) {
                ulonglong2 wv = *reinterpret_cast<const ulonglong2*>(&w_t[k4 * 4 + k][p * 4]);
                acc[p * 2 + 0] = fma2(hh, wv.x, acc[p * 2 + 0]);
                acc[p * 2 + 1] = fma2(hh, wv.y, acc[p * 2 + 1]);
            }
        }
    }
    if (r < NN) {
#pragma unroll
        for (int p = 0; p < 10; p++) {
            float2 lo = unpk(acc[p * 2 + 0]);
            float2 hi = unpk(acc[p * 2 + 1]);
            *reinterpret_cast<float4*>(out + (size_t)r * OC + p * 4) =
                make_float4(lo.x + bs[p * 4 + 0], lo.y + bs[p * 4 + 1],
                            hi.x + bs[p * 4 + 2], hi.y + bs[p * 4 + 3]);
        }
    }
}

// ---------------------------------------------------------------------------
// Launch: gemm1 (writes h0 + zeros) -> spmm_both -> gemm2
// Inputs: x, edge_index(unused), adj_src, adj_dst, adj_val,
//         adj2_src, adj2_dst, adj2_val, fc1_w, fc_out_w, fc_out_b
// ---------------------------------------------------------------------------
extern "C" void kernel_launch(void* const* d_in, const int* in_sizes, int n_in,
                              void* d_out, int out_size) {
    const float* x   = (const float*)d_in[0];
    const int*   a1r = (const int*)  d_in[2];
    const int*   a1c = (const int*)  d_in[3];
    const float* a1v = (const float*)d_in[4];
    const int*   a2r = (const int*)  d_in[5];
    const int*   a2c = (const int*)  d_in[6];
    const float* a2v = (const float*)d_in[7];
    const float* w1  = (const float*)d_in[8];
    const float* w2  = (const float*)d_in[9];
    const float* b2  = (const float*)d_in[10];
    float* out = (float*)d_out;
    const int E1 = in_sizes[4];
    const int E2 = in_sizes[7];

    gemm1<<<(NN + 127) / 128, 256>>>(x, w1);

    int W1 = (E1 + 7) / 8;
    int W2 = (E2 + 7) / 8;
    int Wt = W1 + W2;
    int blocks = (Wt + 7) / 8;          // 8 warps per 256-thread block
    spmm_both<<<blocks, 256>>>(a1r, a1c, a1v, E1, a2r, a2c, a2v, E2, W1, Wt);

    gemm2<<<(NN + 255) / 256, 256>>>(w2, b2, out);
}

// round 3
// speedup vs baseline: 1.5870x; 1.0796x over previous
#include <cuda_runtime.h>
#include <stdint.h>

#define NN   100000
#define INC  256
#define HIDC 64
#define OC   40

// Scratch: compact h0 [N,64] (25.6MB) + projected g1,g2 [N,40] (16MB each).
static __device__ float g_h0[(size_t)NN * HIDC];
static __device__ float g_g1[(size_t)NN * OC];
static __device__ float g_g2[(size_t)NN * OC];

// ---------------- packed fp32 helpers (FFMA2 via PTX fma.rn.f32x2) ----------
__device__ __forceinline__ unsigned long long fma2(unsigned long long a,
                                                   unsigned long long b,
                                                   unsigned long long c) {
    unsigned long long d;
    asm("fma.rn.f32x2 %0, %1, %2, %3;" : "=l"(d) : "l"(a), "l"(b), "l"(c));
    return d;
}
__device__ __forceinline__ unsigned long long dup2(float x) {
    unsigned long long d;
    asm("mov.b64 %0, {%1, %1};" : "=l"(d) : "f"(x));
    return d;
}
__device__ __forceinline__ float2 unpk(unsigned long long v) {
    float2 r;
    asm("mov.b64 {%0, %1}, %2;" : "=f"(r.x), "=f"(r.y) : "l"(v));
    return r;
}

// ---------------------------------------------------------------------------
// GEMM1: h0 = x @ fc1_w^T    x[NN,256], w[64,256] -> g_h0[NN,64]
// Tile 128x64, thread = 8 rows x 4 cols (2 packed pairs), K-chunk 32, FFMA2.
// ---------------------------------------------------------------------------
__global__ __launch_bounds__(256) void gemm1(const float* __restrict__ x,
                                             const float* __restrict__ w) {
    __shared__ __align__(16) float xs[128][36];
    __shared__ __align__(16) float ws_t[32][68];
    const int tid = threadIdx.x;
    const int tx = tid & 15;
    const int ty = tid >> 4;
    const int row0 = blockIdx.x * 128;

    unsigned long long acc0[8], acc1[8];
#pragma unroll
    for (int i = 0; i < 8; i++) { acc0[i] = 0ULL; acc1[i] = 0ULL; }

    for (int k0 = 0; k0 < INC; k0 += 32) {
#pragma unroll
        for (int q = 0; q < 4; q++) {
            int f  = tid + q * 256;
            int k4 = f & 7;
            int r  = f >> 3;
            int gr = min(row0 + r, NN - 1);
            float4 xv = *reinterpret_cast<const float4*>(x + (size_t)gr * INC + k0 + k4 * 4);
            *reinterpret_cast<float4*>(&xs[r][k4 * 4]) = xv;
        }
#pragma unroll
        for (int q = 0; q < 2; q++) {
            int f  = tid + q * 256;
            int k4 = f & 7;
            int n  = f >> 3;
            float4 wv = *reinterpret_cast<const float4*>(w + (size_t)n * INC + k0 + k4 * 4);
            ws_t[k4 * 4 + 0][n] = wv.x;
            ws_t[k4 * 4 + 1][n] = wv.y;
            ws_t[k4 * 4 + 2][n] = wv.z;
            ws_t[k4 * 4 + 3][n] = wv.w;
        }
        __syncthreads();
#pragma unroll 2
        for (int k4 = 0; k4 < 8; k4++) {
            ulonglong2 bb[4];
#pragma unroll
            for (int k = 0; k < 4; k++)
                bb[k] = *reinterpret_cast<const ulonglong2*>(&ws_t[k4 * 4 + k][tx * 4]);
#pragma unroll
            for (int i = 0; i < 8; i++) {
                float4 a4 = *reinterpret_cast<const float4*>(&xs[ty * 8 + i][k4 * 4]);
                unsigned long long aa;
                aa = dup2(a4.x); acc0[i] = fma2(aa, bb[0].x, acc0[i]); acc1[i] = fma2(aa, bb[0].y, acc1[i]);
                aa = dup2(a4.y); acc0[i] = fma2(aa, bb[1].x, acc0[i]); acc1[i] = fma2(aa, bb[1].y, acc1[i]);
                aa = dup2(a4.z); acc0[i] = fma2(aa, bb[2].x, acc0[i]); acc1[i] = fma2(aa, bb[2].y, acc1[i]);
                aa = dup2(a4.w); acc0[i] = fma2(aa, bb[3].x, acc0[i]); acc1[i] = fma2(aa, bb[3].y, acc1[i]);
            }
        }
        __syncthreads();
    }
#pragma unroll
    for (int i = 0; i < 8; i++) {
        int gr = row0 + ty * 8 + i;
        if (gr < NN) {
            float2 lo = unpk(acc0[i]);
            float2 hi = unpk(acc1[i]);
            *reinterpret_cast<float4*>(g_h0 + (size_t)gr * HIDC + tx * 4) =
                make_float4(lo.x, lo.y, hi.x, hi.y);
        }
    }
}

// ---------------------------------------------------------------------------
// PROJ: per node n (thread):
//   out[n] = h0[n] @ W0^T + b        (W0 = fc_out_w[:, 0:64])
//   g1[n]  = h0[n] @ W1^T            (W1 = fc_out_w[:, 64:128])
//   g2[n]  = h0[n] @ W2^T            (W2 = fc_out_w[:, 128:192])
// Weights transposed to smem [k][oc]; broadcast LDS.128; FFMA2.
// ---------------------------------------------------------------------------
__global__ __launch_bounds__(256) void proj(const float* __restrict__ w,
                                            const float* __restrict__ b,
                                            float* __restrict__ out) {
    __shared__ __align__(16) float wt[192][44];   // [k][oc], 176B rows
    __shared__ float bs[OC];
    const int tid = threadIdx.x;
    for (int idx = tid; idx < OC * 192; idx += 256) {
        int o = idx / 192;
        int k = idx - o * 192;
        wt[k][o] = w[idx];
    }
    if (tid < OC) bs[tid] = b[tid];
    __syncthreads();

    const int n  = blockIdx.x * 256 + tid;
    const int nn = min(n, NN - 1);
    const float* hrow = g_h0 + (size_t)nn * HIDC;

    float h[HIDC];
#pragma unroll
    for (int k4 = 0; k4 < 16; k4++) {
        float4 h4 = *reinterpret_cast<const float4*>(hrow + k4 * 4);
        h[k4 * 4 + 0] = h4.x; h[k4 * 4 + 1] = h4.y;
        h[k4 * 4 + 2] = h4.z; h[k4 * 4 + 3] = h4.w;
    }

#pragma unroll
    for (int s = 0; s < 3; s++) {
        unsigned long long acc[20];
#pragma unroll
        for (int p = 0; p < 20; p++) acc[p] = 0ULL;
#pragma unroll 4
        for (int k = 0; k < HIDC; k++) {
            unsigned long long hh = dup2(h[k]);
            const float* wrow = &wt[s * 64 + k][0];
#pragma unroll
            for (int p = 0; p < 10; p++) {
                ulonglong2 wv = *reinterpret_cast<const ulonglong2*>(wrow + p * 4);
                acc[p * 2 + 0] = fma2(hh, wv.x, acc[p * 2 + 0]);
                acc[p * 2 + 1] = fma2(hh, wv.y, acc[p * 2 + 1]);
            }
        }
        if (n < NN) {
            float* dst = (s == 0) ? (out + (size_t)n * OC)
                       : (s == 1) ? (g_g1 + (size_t)n * OC)
                                  : (g_g2 + (size_t)n * OC);
#pragma unroll
            for (int p = 0; p < 10; p++) {
                float2 lo = unpk(acc[p * 2 + 0]);
                float2 hi = unpk(acc[p * 2 + 1]);
                float4 v = make_float4(lo.x, lo.y, hi.x, hi.y);
                if (s == 0) {
                    v.x += bs[p * 4 + 0]; v.y += bs[p * 4 + 1];
                    v.z += bs[p * 4 + 2]; v.w += bs[p * 4 + 3];
                }
                *reinterpret_cast<float4*>(dst + p * 4) = v;
            }
        }
    }
}

// ---------------------------------------------------------------------------
// SPMM40 (both graphs, one launch):
//   out[src[e]] += val[e] * G[dst[e]]   (G = g1 for graph1, g2 for graph2)
// Warp = 3 edges x 10 lanes x float4 (40 floats). Lanes 0..2 load edge data,
// shfl distributes. Vectorized red.global.add into L2-hot out (16MB).
// ---------------------------------------------------------------------------
__global__ void spmm40(const int* __restrict__ r1, const int* __restrict__ c1,
                       const float* __restrict__ v1, int E1,
                       const int* __restrict__ r2, const int* __restrict__ c2,
                       const float* __restrict__ v2, int E2,
                       int W1, int Wt, float* __restrict__ out) {
    int gw = (int)((blockIdx.x * blockDim.x + threadIdx.x) >> 5);
    if (gw >= Wt) return;
    const int* R; const int* C; const float* V; const float* G; int E, e0;
    if (gw < W1) { R = r1; C = c1; V = v1; G = g_g1; E = E1; e0 = gw * 3; }
    else         { R = r2; C = c2; V = v2; G = g_g2; E = E2; e0 = (gw - W1) * 3; }

    const int lane = threadIdx.x & 31;
    int   rr = 0, cc = 0;
    float vv = 0.f;
    if (lane < 3) {
        int e = e0 + lane;
        if (e < E) {
            rr = __ldg(R + e);
            cc = __ldg(C + e);
            vv = __ldg(V + e);
        }
    }
    const int g    = (lane >= 20) ? 2 : ((lane >= 10) ? 1 : 0);
    const int slot = lane - g * 10;
    int   c = __shfl_sync(0xffffffffu, cc, g);
    int   r = __shfl_sync(0xffffffffu, rr, g);
    float v = __shfl_sync(0xffffffffu, vv, g);
    if (lane < 30) {
        float4 h = *reinterpret_cast<const float4*>(G + (size_t)c * OC + slot * 4);
        float4 p = make_float4(h.x * v, h.y * v, h.z * v, h.w * v);
        float* dst = out + (size_t)r * OC + slot * 4;
        asm volatile("red.global.add.v4.f32 [%0], {%1,%2,%3,%4};"
                     :: "l"(dst), "f"(p.x), "f"(p.y), "f"(p.z), "f"(p.w)
                     : "memory");
    }
}

// ---------------------------------------------------------------------------
// Launch: gemm1 -> proj (writes out-init + g1 + g2) -> spmm40 (reduce into out)
// Inputs: x, edge_index(unused), adj_src, adj_dst, adj_val,
//         adj2_src, adj2_dst, adj2_val, fc1_w, fc_out_w, fc_out_b
// ---------------------------------------------------------------------------
extern "C" void kernel_launch(void* const* d_in, const int* in_sizes, int n_in,
                              void* d_out, int out_size) {
    const float* x   = (const float*)d_in[0];
    const int*   a1r = (const int*)  d_in[2];
    const int*   a1c = (const int*)  d_in[3];
    const float* a1v = (const float*)d_in[4];
    const int*   a2r = (const int*)  d_in[5];
    const int*   a2c = (const int*)  d_in[6];
    const float* a2v = (const float*)d_in[7];
    const float* w1  = (const float*)d_in[8];
    const float* w2  = (const float*)d_in[9];
    const float* b2  = (const float*)d_in[10];
    float* out = (float*)d_out;
    const int E1 = in_sizes[4];
    const int E2 = in_sizes[7];

    gemm1<<<(NN + 127) / 128, 256>>>(x, w1);
    proj<<<(NN + 255) / 256, 256>>>(w2, b2, out);

    int W1 = (E1 + 2) / 3;
    int W2 = (E2 + 2) / 3;
    int Wt = W1 + W2;
    int blocks = (Wt + 7) / 8;          // 8 warps / 256-thread block
    spmm40<<<blocks, 256>>>(a1r, a1c, a1v, E1, a2r, a2c, a2v, E2, W1, Wt, out);
}

// round 4
// speedup vs baseline: 1.5903x; 1.0021x over previous
#include <cuda_runtime.h>
#include <stdint.h>

#define NN   100000
#define INC  256
#define HIDC 64
#define OC   40

// h0 [N,64] + split-layout projected vectors: A-part [N,32] (128B rows),
// B-part [N,8] (32B rows). outA/outB are the atomic reduction targets.
static __device__ float g_h0 [(size_t)NN * HIDC];
static __device__ float g_gA1[(size_t)NN * 32];
static __device__ float g_gB1[(size_t)NN * 8];
static __device__ float g_gA2[(size_t)NN * 32];
static __device__ float g_gB2[(size_t)NN * 8];
static __device__ float g_oA [(size_t)NN * 32];
static __device__ float g_oB [(size_t)NN * 8];

// ---------------- packed fp32 helpers (FFMA2 via PTX fma.rn.f32x2) ----------
__device__ __forceinline__ unsigned long long fma2(unsigned long long a,
                                                   unsigned long long b,
                                                   unsigned long long c) {
    unsigned long long d;
    asm("fma.rn.f32x2 %0, %1, %2, %3;" : "=l"(d) : "l"(a), "l"(b), "l"(c));
    return d;
}
__device__ __forceinline__ unsigned long long dup2(float x) {
    unsigned long long d;
    asm("mov.b64 %0, {%1, %1};" : "=l"(d) : "f"(x));
    return d;
}
__device__ __forceinline__ float2 unpk(unsigned long long v) {
    float2 r;
    asm("mov.b64 {%0, %1}, %2;" : "=f"(r.x), "=f"(r.y) : "l"(v));
    return r;
}

// ---------------------------------------------------------------------------
// GEMM1: h0 = x @ fc1_w^T    x[NN,256], w[64,256] -> g_h0[NN,64]
// ---------------------------------------------------------------------------
__global__ __launch_bounds__(256) void gemm1(const float* __restrict__ x,
                                             const float* __restrict__ w) {
    __shared__ __align__(16) float xs[128][36];
    __shared__ __align__(16) float ws_t[32][68];
    const int tid = threadIdx.x;
    const int tx = tid & 15;
    const int ty = tid >> 4;
    const int row0 = blockIdx.x * 128;

    unsigned long long acc0[8], acc1[8];
#pragma unroll
    for (int i = 0; i < 8; i++) { acc0[i] = 0ULL; acc1[i] = 0ULL; }

    for (int k0 = 0; k0 < INC; k0 += 32) {
#pragma unroll
        for (int q = 0; q < 4; q++) {
            int f  = tid + q * 256;
            int k4 = f & 7;
            int r  = f >> 3;
            int gr = min(row0 + r, NN - 1);
            float4 xv = *reinterpret_cast<const float4*>(x + (size_t)gr * INC + k0 + k4 * 4);
            *reinterpret_cast<float4*>(&xs[r][k4 * 4]) = xv;
        }
#pragma unroll
        for (int q = 0; q < 2; q++) {
            int f  = tid + q * 256;
            int k4 = f & 7;
            int n  = f >> 3;
            float4 wv = *reinterpret_cast<const float4*>(w + (size_t)n * INC + k0 + k4 * 4);
            ws_t[k4 * 4 + 0][n] = wv.x;
            ws_t[k4 * 4 + 1][n] = wv.y;
            ws_t[k4 * 4 + 2][n] = wv.z;
            ws_t[k4 * 4 + 3][n] = wv.w;
        }
        __syncthreads();
#pragma unroll 2
        for (int k4 = 0; k4 < 8; k4++) {
            ulonglong2 bb[4];
#pragma unroll
            for (int k = 0; k < 4; k++)
                bb[k] = *reinterpret_cast<const ulonglong2*>(&ws_t[k4 * 4 + k][tx * 4]);
#pragma unroll
            for (int i = 0; i < 8; i++) {
                float4 a4 = *reinterpret_cast<const float4*>(&xs[ty * 8 + i][k4 * 4]);
                unsigned long long aa;
                aa = dup2(a4.x); acc0[i] = fma2(aa, bb[0].x, acc0[i]); acc1[i] = fma2(aa, bb[0].y, acc1[i]);
                aa = dup2(a4.y); acc0[i] = fma2(aa, bb[1].x, acc0[i]); acc1[i] = fma2(aa, bb[1].y, acc1[i]);
                aa = dup2(a4.z); acc0[i] = fma2(aa, bb[2].x, acc0[i]); acc1[i] = fma2(aa, bb[2].y, acc1[i]);
                aa = dup2(a4.w); acc0[i] = fma2(aa, bb[3].x, acc0[i]); acc1[i] = fma2(aa, bb[3].y, acc1[i]);
            }
        }
        __syncthreads();
    }
#pragma unroll
    for (int i = 0; i < 8; i++) {
        int gr = row0 + ty * 8 + i;
        if (gr < NN) {
            float2 lo = unpk(acc0[i]);
            float2 hi = unpk(acc1[i]);
            *reinterpret_cast<float4*>(g_h0 + (size_t)gr * HIDC + tx * 4) =
                make_float4(lo.x, lo.y, hi.x, hi.y);
        }
    }
}

// ---------------------------------------------------------------------------
// PROJ: per node n:  init = h0@W0^T + b -> oA/oB
//                    g1   = h0@W1^T     -> gA1/gB1
//                    g2   = h0@W2^T     -> gA2/gB2
// ---------------------------------------------------------------------------
__global__ __launch_bounds__(256) void proj(const float* __restrict__ w,
                                            const float* __restrict__ b) {
    __shared__ __align__(16) float wt[192][44];
    __shared__ float bs[OC];
    const int tid = threadIdx.x;
    for (int idx = tid; idx < OC * 192; idx += 256) {
        int o = idx / 192;
        int k = idx - o * 192;
        wt[k][o] = w[idx];
    }
    if (tid < OC) bs[tid] = b[tid];
    __syncthreads();

    const int n  = blockIdx.x * 256 + tid;
    const int nn = min(n, NN - 1);
    const float* hrow = g_h0 + (size_t)nn * HIDC;

    float h[HIDC];
#pragma unroll
    for (int k4 = 0; k4 < 16; k4++) {
        float4 h4 = *reinterpret_cast<const float4*>(hrow + k4 * 4);
        h[k4 * 4 + 0] = h4.x; h[k4 * 4 + 1] = h4.y;
        h[k4 * 4 + 2] = h4.z; h[k4 * 4 + 3] = h4.w;
    }

#pragma unroll
    for (int s = 0; s < 3; s++) {
        unsigned long long acc[20];
#pragma unroll
        for (int p = 0; p < 20; p++) acc[p] = 0ULL;
#pragma unroll 4
        for (int k = 0; k < HIDC; k++) {
            unsigned long long hh = dup2(h[k]);
            const float* wrow = &wt[s * 64 + k][0];
#pragma unroll
            for (int p = 0; p < 10; p++) {
                ulonglong2 wv = *reinterpret_cast<const ulonglong2*>(wrow + p * 4);
                acc[p * 2 + 0] = fma2(hh, wv.x, acc[p * 2 + 0]);
                acc[p * 2 + 1] = fma2(hh, wv.y, acc[p * 2 + 1]);
            }
        }
        if (n < NN) {
            float* dA = (s == 0) ? g_oA : (s == 1) ? g_gA1 : g_gA2;
            float* dB = (s == 0) ? g_oB : (s == 1) ? g_gB1 : g_gB2;
#pragma unroll
            for (int p = 0; p < 10; p++) {
                float2 lo = unpk(acc[p * 2 + 0]);
                float2 hi = unpk(acc[p * 2 + 1]);
                float4 v = make_float4(lo.x, lo.y, hi.x, hi.y);
                if (s == 0) {
                    v.x += bs[p * 4 + 0]; v.y += bs[p * 4 + 1];
                    v.z += bs[p * 4 + 2]; v.w += bs[p * 4 + 3];
                }
                if (p < 8)
                    *reinterpret_cast<float4*>(dA + (size_t)n * 32 + p * 4) = v;
                else
                    *reinterpret_cast<float4*>(dB + (size_t)n * 8 + (p - 8) * 4) = v;
            }
        }
    }
}

// ---------------------------------------------------------------------------
// SPMM (both graphs): oA[r] += v*gA[c] (128B rows), oB[r] += v*gB[c] (32B rows)
// Warp = 4 edges. Lanes 0..3 load (r,c,v); shfl distributes.
// A: 4 groups x 8 lanes, each gather/red = exactly one 128B line.
// B: lanes 0..7 (2 lanes/edge), each gather/red = one 32B sector.
// ---------------------------------------------------------------------------
__global__ void spmm(const int* __restrict__ r1, const int* __restrict__ c1,
                     const float* __restrict__ v1, int E1,
                     const int* __restrict__ r2, const int* __restrict__ c2,
                     const float* __restrict__ v2, int E2, int W1, int Wt) {
    int gw = (int)((blockIdx.x * blockDim.x + threadIdx.x) >> 5);
    if (gw >= Wt) return;
    const int* R; const int* C; const float* V;
    const float* GA; const float* GB; int E, e0;
    if (gw < W1) { R = r1; C = c1; V = v1; GA = g_gA1; GB = g_gB1; E = E1; e0 = gw * 4; }
    else         { R = r2; C = c2; V = v2; GA = g_gA2; GB = g_gB2; E = E2; e0 = (gw - W1) * 4; }

    const int lane = threadIdx.x & 31;
    int   rr = 0, cc = 0;
    float vv = 0.f;
    if (lane < 4) {
        int e  = e0 + lane;
        int ec = min(e, E - 1);
        rr = __ldg(R + ec);
        cc = __ldg(C + ec);
        vv = (e < E) ? __ldg(V + ec) : 0.f;   // v=0 makes OOB edges no-ops
    }

    // ---- A part: all 32 lanes, group g = lane>>3 handles edge e0+g ----
    {
        const int g  = lane >> 3;
        const int sl = lane & 7;
        int   c = __shfl_sync(0xffffffffu, cc, g);
        int   r = __shfl_sync(0xffffffffu, rr, g);
        float v = __shfl_sync(0xffffffffu, vv, g);
        float4 h = *reinterpret_cast<const float4*>(GA + (size_t)c * 32 + sl * 4);
        float4 p = make_float4(h.x * v, h.y * v, h.z * v, h.w * v);
        float* dst = g_oA + (size_t)r * 32 + sl * 4;
        asm volatile("red.global.add.v4.f32 [%0], {%1,%2,%3,%4};"
                     :: "l"(dst), "f"(p.x), "f"(p.y), "f"(p.z), "f"(p.w)
                     : "memory");
    }
    // ---- B part: lanes 0..7, pair (lane>>1) handles edge, slot = lane&1 ----
    {
        const int g  = (lane >> 1) & 3;
        const int sl = lane & 1;
        int   c = __shfl_sync(0xffffffffu, cc, g);
        int   r = __shfl_sync(0xffffffffu, rr, g);
        float v = __shfl_sync(0xffffffffu, vv, g);
        if (lane < 8) {
            float4 h = *reinterpret_cast<const float4*>(GB + (size_t)c * 8 + sl * 4);
            float4 p = make_float4(h.x * v, h.y * v, h.z * v, h.w * v);
            float* dst = g_oB + (size_t)r * 8 + sl * 4;
            asm volatile("red.global.add.v4.f32 [%0], {%1,%2,%3,%4};"
                         :: "l"(dst), "f"(p.x), "f"(p.y), "f"(p.z), "f"(p.w)
                         : "memory");
        }
    }
}

// ---------------------------------------------------------------------------
// MERGE: out[n][0:40] = oA[n][0:32] || oB[n][0:8]
// ---------------------------------------------------------------------------
__global__ void merge(float* __restrict__ out) {
    int idx = blockIdx.x * blockDim.x + threadIdx.x;   // float4 slots, NN*10
    if (idx >= NN * 10) return;
    int n = idx / 10;
    int s = idx - n * 10;
    float4 v = (s < 8)
        ? *reinterpret_cast<const float4*>(g_oA + (size_t)n * 32 + s * 4)
        : *reinterpret_cast<const float4*>(g_oB + (size_t)n * 8 + (s - 8) * 4);
    *reinterpret_cast<float4*>(out + (size_t)n * OC + s * 4) = v;
}

// ---------------------------------------------------------------------------
// Launch: gemm1 -> proj -> spmm -> merge
// ---------------------------------------------------------------------------
extern "C" void kernel_launch(void* const* d_in, const int* in_sizes, int n_in,
                              void* d_out, int out_size) {
    const float* x   = (const float*)d_in[0];
    const int*   a1r = (const int*)  d_in[2];
    const int*   a1c = (const int*)  d_in[3];
    const float* a1v = (const float*)d_in[4];
    const int*   a2r = (const int*)  d_in[5];
    const int*   a2c = (const int*)  d_in[6];
    const float* a2v = (const float*)d_in[7];
    const float* w1  = (const float*)d_in[8];
    const float* w2  = (const float*)d_in[9];
    const float* b2  = (const float*)d_in[10];
    float* out = (float*)d_out;
    const int E1 = in_sizes[4];
    const int E2 = in_sizes[7];

    gemm1<<<(NN + 127) / 128, 256>>>(x, w1);
    proj<<<(NN + 255) / 256, 256>>>(w2, b2);

    int W1 = (E1 + 3) / 4;
    int W2 = (E2 + 3) / 4;
    int Wt = W1 + W2;
    int blocks = (Wt + 7) / 8;
    spmm<<<blocks, 256>>>(a1r, a1c, a1v, E1, a2r, a2c, a2v, E2, W1, Wt);

    merge<<<(NN * 10 + 255) / 256, 256>>>(out);
}